// round 1
// baseline (speedup 1.0000x reference)
#include <cuda_runtime.h>
#include <math.h>

// ---------------- problem constants ----------------
constexpr int B_  = 16;
constexpr int D_  = 256;
constexpr int NH_ = 512;
constexpr int NV_ = 256;
constexpr int W_  = 768;          // NH + NV
constexpr int L_  = 4;
constexpr int H_  = 8;
constexpr int A_  = 64;
constexpr int HA_ = 512;
constexpr int M_  = 512;
constexpr int R_  = 128;
constexpr int GHA_ = L_ * H_ * A_;   // 2048
constexpr float EPS_   = 1e-5f;
constexpr float SCALE_ = 0.125f;     // A^-0.5

// ---------------- device scratch (no allocs allowed) ----------------
__device__ float g_ki   [B_ * W_ * (D_ + 1)];        // 12.6 MB
__device__ float g_kwT  [(D_ + 1) * GHA_];           // 2.1 MB
__device__ float g_vwT  [(D_ + 1) * GHA_];
__device__ float g_att  [B_ * NV_ * HA_];            // 8 MB
__device__ float g_keys [(size_t)B_ * W_ * GHA_];    // 100 MB
__device__ float g_vals [(size_t)B_ * W_ * GHA_];    // 100 MB
__device__ float g_scores[(size_t)B_ * H_ * NV_ * W_]; // 100 MB
__device__ float g_res  [B_ * NV_ * HA_];
__device__ float g_ff1  [B_ * NV_ * M_];
__device__ float g_ff2  [B_ * NV_ * M_];
__device__ float g_logits[B_ * NV_ * R_];

// ---------------- build ki = [hist||u ; pred||u]  [B, W, 257] ----------------
__global__ void build_ki(const float* __restrict__ hist, const float* __restrict__ hu,
                         const float* __restrict__ pred, const float* __restrict__ pu) {
    int idx = blockIdx.x * blockDim.x + threadIdx.x;
    const int total = B_ * W_ * (D_ + 1);
    if (idx >= total) return;
    int d = idx % (D_ + 1);
    int w = (idx / (D_ + 1)) % W_;
    int b = idx / ((D_ + 1) * W_);
    float v;
    if (d < D_) {
        v = (w < NH_) ? hist[((size_t)(b * NH_ + w)) * D_ + d]
                      : pred[((size_t)(b * NV_ + (w - NH_))) * D_ + d];
    } else {
        v = (w < NH_) ? hu[b * NH_ + w] : pu[b * NV_ + (w - NH_)];
    }
    g_ki[idx] = v;
}

// key_w [L,H,257,A] -> [257, L*H*A]
__global__ void transpose_w(const float* __restrict__ src, float* __restrict__ dst) {
    int idx = blockIdx.x * blockDim.x + threadIdx.x;
    const int total = (D_ + 1) * GHA_;
    if (idx >= total) return;
    int c = idx % GHA_;
    int d = idx / GHA_;
    int g = c >> 6;        // l*H + h
    int a = c & 63;
    dst[idx] = src[((size_t)(g * (D_ + 1) + d)) * A_ + a];
}

// ---------------- generic SGEMM: C[MxN] = A[MxK] @ B[KxN] + bias (+relu) ----------------
template <bool RELU>
__global__ void sgemm_bias(const float* __restrict__ Am, const float* __restrict__ Bm,
                           const float* __restrict__ bias, float* __restrict__ Cm,
                           int Mr, int N, int K) {
    __shared__ float As[16][65];
    __shared__ float Bs[16][65];
    const int bm = blockIdx.y * 64;
    const int bn = blockIdx.x * 64;
    const int t  = threadIdx.x;
    const int ty = t >> 4, tx = t & 15;
    float acc[4][4] = {};
    for (int k0 = 0; k0 < K; k0 += 16) {
#pragma unroll
        for (int it = 0; it < 4; it++) {
            int p = t + it * 256;
            int i = p >> 4, j = p & 15;
            float v = 0.f;
            if (k0 + j < K && bm + i < Mr) v = Am[(size_t)(bm + i) * K + k0 + j];
            As[j][i] = v;
        }
#pragma unroll
        for (int it = 0; it < 4; it++) {
            int p = t + it * 256;
            int j = p >> 6, i = p & 63;
            float v = 0.f;
            if (k0 + j < K && bn + i < N) v = Bm[(size_t)(k0 + j) * N + bn + i];
            Bs[j][i] = v;
        }
        __syncthreads();
#pragma unroll
        for (int j = 0; j < 16; j++) {
            float af[4], bf[4];
#pragma unroll
            for (int r = 0; r < 4; r++) af[r] = As[j][ty * 4 + r];
#pragma unroll
            for (int c = 0; c < 4; c++) bf[c] = Bs[j][tx * 4 + c];
#pragma unroll
            for (int r = 0; r < 4; r++)
#pragma unroll
                for (int c = 0; c < 4; c++)
                    acc[r][c] = fmaf(af[r], bf[c], acc[r][c]);
        }
        __syncthreads();
    }
#pragma unroll
    for (int r = 0; r < 4; r++) {
        int m = bm + ty * 4 + r;
        if (m >= Mr) continue;
#pragma unroll
        for (int c = 0; c < 4; c++) {
            int n = bn + tx * 4 + c;
            if (n >= N) continue;
            float v = acc[r][c] + bias[n];
            if (RELU) v = fmaxf(v, 0.f);
            Cm[(size_t)m * N + n] = v;
        }
    }
}

// ---------------- attention: scores = scale * Q @ K^T with causal mask ----------------
__global__ void attn_scores(int l) {
    const int wt = blockIdx.x;   // 0..11
    const int vt = blockIdx.y;   // 0..3
    const int bh = blockIdx.z;   // 0..127
    const int b = bh >> 3, h = bh & 7;
    const int t = threadIdx.x;
    const int ty = t >> 4, tx = t & 15;
    float* srow = g_scores + ((size_t)bh * NV_ + vt * 64) * W_ + wt * 64;

    if (wt >= vt + 9) {  // tile fully masked
#pragma unroll
        for (int r = 0; r < 4; r++)
#pragma unroll
            for (int c = 0; c < 4; c++)
                srow[(size_t)(ty * 4 + r) * W_ + tx * 4 + c] = -INFINITY;
        return;
    }

    __shared__ float Qs[64][65];
    __shared__ float Ks[64][65];
#pragma unroll
    for (int it = 0; it < 16; it++) {
        int p = t + it * 256;
        int i = p >> 6, a = p & 63;
        Qs[i][a] = g_att[((size_t)(b * NV_ + vt * 64 + i)) * HA_ + h * 64 + a];
        Ks[i][a] = g_keys[((size_t)(b * W_ + wt * 64 + i)) * GHA_ + (l * H_ + h) * A_ + a];
    }
    __syncthreads();
    float acc[4][4] = {};
#pragma unroll
    for (int a = 0; a < 64; a++) {
        float qf[4], kf[4];
#pragma unroll
        for (int r = 0; r < 4; r++) qf[r] = Qs[ty * 4 + r][a];
#pragma unroll
        for (int c = 0; c < 4; c++) kf[c] = Ks[tx * 4 + c][a];
#pragma unroll
        for (int r = 0; r < 4; r++)
#pragma unroll
            for (int c = 0; c < 4; c++)
                acc[r][c] = fmaf(qf[r], kf[c], acc[r][c]);
    }
#pragma unroll
    for (int r = 0; r < 4; r++) {
        int v = vt * 64 + ty * 4 + r;
#pragma unroll
        for (int c = 0; c < 4; c++) {
            int w = wt * 64 + tx * 4 + c;
            float s = (w >= NH_ + v) ? -INFINITY : acc[r][c] * SCALE_;
            srow[(size_t)(ty * 4 + r) * W_ + tx * 4 + c] = s;
        }
    }
}

// ---------------- softmax over W (row-wise, handles -inf tail) ----------------
__global__ void softmax_rows() {
    const int row = blockIdx.x;  // B*H*NV
    float* p = g_scores + (size_t)row * W_;
    const int t = threadIdx.x;   // 128
    float vals[6];
    float m = -INFINITY;
#pragma unroll
    for (int i = 0; i < 6; i++) { vals[i] = p[t + i * 128]; m = fmaxf(m, vals[i]); }
    __shared__ float red[128];
    red[t] = m; __syncthreads();
    for (int s = 64; s > 0; s >>= 1) { if (t < s) red[t] = fmaxf(red[t], red[t + s]); __syncthreads(); }
    m = red[0];
    __syncthreads();
    float sum = 0.f;
#pragma unroll
    for (int i = 0; i < 6; i++) { vals[i] = __expf(vals[i] - m); sum += vals[i]; }
    red[t] = sum; __syncthreads();
    for (int s = 64; s > 0; s >>= 1) { if (t < s) red[t] += red[t + s]; __syncthreads(); }
    float inv = 1.f / red[0];
#pragma unroll
    for (int i = 0; i < 6; i++) p[t + i * 128] = vals[i] * inv;
}

// ---------------- attention out: res = att + P @ V ----------------
__global__ void attn_av(int l) {
    const int vt = blockIdx.x;   // 0..3
    const int bh = blockIdx.y;   // 0..127
    const int b = bh >> 3, h = bh & 7;
    const int t = threadIdx.x;
    const int ty = t >> 4, tx = t & 15;
    __shared__ float Ps[64][65];
    __shared__ float Vs[64][65];
    float acc[4][4] = {};
    const int wmax = vt + 9;     // beyond this, P == 0
    for (int wt = 0; wt < wmax; wt++) {
#pragma unroll
        for (int it = 0; it < 16; it++) {
            int p = t + it * 256;
            int i = p >> 6, j = p & 63;
            Ps[i][j] = g_scores[((size_t)bh * NV_ + vt * 64 + i) * W_ + wt * 64 + j];
            Vs[i][j] = g_vals[((size_t)(b * W_ + wt * 64 + i)) * GHA_ + (l * H_ + h) * A_ + j];
        }
        __syncthreads();
#pragma unroll
        for (int j = 0; j < 64; j++) {
            float pf[4], vf[4];
#pragma unroll
            for (int r = 0; r < 4; r++) pf[r] = Ps[ty * 4 + r][j];
#pragma unroll
            for (int c = 0; c < 4; c++) vf[c] = Vs[j][tx * 4 + c];
#pragma unroll
            for (int r = 0; r < 4; r++)
#pragma unroll
                for (int c = 0; c < 4; c++)
                    acc[r][c] = fmaf(pf[r], vf[c], acc[r][c]);
        }
        __syncthreads();
    }
#pragma unroll
    for (int r = 0; r < 4; r++) {
        int v = vt * 64 + ty * 4 + r;
#pragma unroll
        for (int c = 0; c < 4; c++) {
            int a = tx * 4 + c;
            size_t o = ((size_t)(b * NV_ + v)) * HA_ + h * 64 + a;
            g_res[o] = g_att[o] + acc[r][c];
        }
    }
}

// ---------------- layernorm: out = g * norm(base + delta) + beta ----------------
__global__ void ln_kernel(const float* __restrict__ base, const float* __restrict__ delta,
                          const float* __restrict__ gamma, const float* __restrict__ beta,
                          float* __restrict__ out) {
    const int row = blockIdx.x;  // B*NV
    const int t = threadIdx.x;   // 256
    const float* br = base + (size_t)row * HA_;
    float x0 = br[t];
    float x1 = br[t + 256];
    if (delta) {
        const float* dr = delta + (size_t)row * HA_;
        x0 += dr[t];
        x1 += dr[t + 256];
    }
    __shared__ float red[256];
    red[t] = x0 + x1; __syncthreads();
    for (int s = 128; s > 0; s >>= 1) { if (t < s) red[t] += red[t + s]; __syncthreads(); }
    float mean = red[0] * (1.f / HA_);
    __syncthreads();
    float d0 = x0 - mean, d1 = x1 - mean;
    red[t] = d0 * d0 + d1 * d1; __syncthreads();
    for (int s = 128; s > 0; s >>= 1) { if (t < s) red[t] += red[t + s]; __syncthreads(); }
    float inv = rsqrtf(red[0] * (1.f / HA_) + EPS_);
    out[(size_t)row * HA_ + t]       = gamma[t]       * (d0 * inv) + beta[t];
    out[(size_t)row * HA_ + t + 256] = gamma[t + 256] * (d1 * inv) + beta[t + 256];
}

// ---------------- final loss reduction (deterministic, one CTA per batch) ----------------
__global__ void loss_kernel(const float* __restrict__ pu, float* __restrict__ out) {
    const int b = blockIdx.x;
    const int t = threadIdx.x;           // 256 = 8 warps
    const int warp = t >> 5, lane = t & 31;
    const float LOG_R = logf((float)R_);
    float accum = 0.f;
    for (int v = 1 + warp; v < NV_; v += 8) {
        const float* lr = g_logits + ((size_t)(b * NV_ + v)) * R_;
        float lv[4];
        float m = -INFINITY;
#pragma unroll
        for (int i = 0; i < 4; i++) { lv[i] = lr[lane + i * 32]; m = fmaxf(m, lv[i]); }
#pragma unroll
        for (int o = 16; o > 0; o >>= 1) m = fmaxf(m, __shfl_xor_sync(0xffffffffu, m, o));
        float se = 0.f;
#pragma unroll
        for (int i = 0; i < 4; i++) se += expf(lv[i] - m);
#pragma unroll
        for (int o = 16; o > 0; o >>= 1) se += __shfl_xor_sync(0xffffffffu, se, o);
        if (lane == 0) {
            float lse = m + logf(se);
            int tgt = (int)floorf(pu[b * NV_ + v] * (float)R_);
            tgt = min(max(tgt, 0), R_ - 1);
            accum += lse - lr[tgt] - LOG_R;
        }
    }
    __shared__ float red[8];
    if (lane == 0) red[warp] = accum;
    __syncthreads();
    if (t == 0) {
        float s = 0.f;
#pragma unroll
        for (int i = 0; i < 8; i++) s += red[i];
        out[b] = s;
    }
}

// ---------------- host launch ----------------
static float* sym_addr(const void* sym) {
    void* p = nullptr;
    cudaGetSymbolAddress(&p, sym);
    return (float*)p;
}

extern "C" void kernel_launch(void* const* d_in, const int* in_sizes, int n_in,
                              void* d_out, int out_size) {
    (void)in_sizes; (void)n_in; (void)out_size;
    const float* hist  = (const float*)d_in[0];
    const float* hu    = (const float*)d_in[1];
    const float* pred  = (const float*)d_in[2];
    const float* pu    = (const float*)d_in[3];
    const float* ds_w  = (const float*)d_in[4];
    const float* ds_b  = (const float*)d_in[5];
    const float* key_w = (const float*)d_in[6];
    const float* key_b = (const float*)d_in[7];
    const float* val_w = (const float*)d_in[8];
    const float* val_b = (const float*)d_in[9];
    const float* ln1_g = (const float*)d_in[10];
    const float* ln1_b = (const float*)d_in[11];
    const float* ln2_g = (const float*)d_in[12];
    const float* ln2_b = (const float*)d_in[13];
    const float* ff_w1 = (const float*)d_in[14];
    const float* ff_b1 = (const float*)d_in[15];
    const float* ff_w2 = (const float*)d_in[16];
    const float* ff_b2 = (const float*)d_in[17];
    const float* ff_w3 = (const float*)d_in[18];
    const float* ff_b3 = (const float*)d_in[19];
    const float* de_w  = (const float*)d_in[20];
    const float* de_b  = (const float*)d_in[21];
    float* out = (float*)d_out;

    float* ki    = sym_addr(g_ki);
    float* kwT   = sym_addr(g_kwT);
    float* vwT   = sym_addr(g_vwT);
    float* att   = sym_addr(g_att);
    float* keys  = sym_addr(g_keys);
    float* vals  = sym_addr(g_vals);
    float* res   = sym_addr(g_res);
    float* ff1   = sym_addr(g_ff1);
    float* ff2   = sym_addr(g_ff2);
    float* logit = sym_addr(g_logits);

    // 1. inputs
    {
        int total = B_ * W_ * (D_ + 1);
        build_ki<<<(total + 255) / 256, 256>>>(hist, hu, pred, pu);
    }
    {
        int total = (D_ + 1) * GHA_;
        transpose_w<<<(total + 255) / 256, 256>>>(key_w, kwT);
        transpose_w<<<(total + 255) / 256, 256>>>(val_w, vwT);
    }
    // 2. att = pred @ ds_w + ds_b   [4096, 512]
    sgemm_bias<false><<<dim3(HA_ / 64, (B_ * NV_) / 64), 256>>>(pred, ds_w, ds_b, att,
                                                                B_ * NV_, HA_, D_);
    // 3. keys / vals = ki @ kwT + bias  [12288, 2048]
    sgemm_bias<false><<<dim3(GHA_ / 64, (B_ * W_) / 64), 256>>>(ki, kwT, key_b, keys,
                                                                B_ * W_, GHA_, D_ + 1);
    sgemm_bias<false><<<dim3(GHA_ / 64, (B_ * W_) / 64), 256>>>(ki, vwT, val_b, vals,
                                                                B_ * W_, GHA_, D_ + 1);
    // 4. layers
    for (int l = 0; l < L_; l++) {
        attn_scores<<<dim3(W_ / 64, NV_ / 64, B_ * H_), 256>>>(l);
        softmax_rows<<<B_ * H_ * NV_, 128>>>();
        attn_av<<<dim3(NV_ / 64, B_ * H_), 256>>>(l);
        ln_kernel<<<B_ * NV_, 256>>>(res, nullptr, ln1_g + l * HA_, ln1_b + l * HA_, att);
        sgemm_bias<true><<<dim3(M_ / 64, (B_ * NV_) / 64), 256>>>(att, ff_w1 + (size_t)l * HA_ * M_,
                                                                  ff_b1 + l * M_, ff1,
                                                                  B_ * NV_, M_, HA_);
        sgemm_bias<true><<<dim3(M_ / 64, (B_ * NV_) / 64), 256>>>(ff1, ff_w2 + (size_t)l * M_ * M_,
                                                                  ff_b2 + l * M_, ff2,
                                                                  B_ * NV_, M_, M_);
        sgemm_bias<false><<<dim3(HA_ / 64, (B_ * NV_) / 64), 256>>>(ff2, ff_w3 + (size_t)l * M_ * HA_,
                                                                    ff_b3 + l * HA_, res,
                                                                    B_ * NV_, HA_, M_);
        ln_kernel<<<B_ * NV_, 256>>>(att, res, ln2_g + l * HA_, ln2_b + l * HA_, att);
    }
    // 5. logits + loss
    sgemm_bias<false><<<dim3(R_ / 64, (B_ * NV_) / 64), 256>>>(att, de_w, de_b, logit,
                                                               B_ * NV_, R_, HA_);
    loss_kernel<<<B_, 256>>>(pu, out);
}